// round 12
// baseline (speedup 1.0000x reference)
#include <cuda_runtime.h>
#include <math.h>
#include <stdint.h>

#define BATCH 8
#define C1    192
#define C3    576
#define HEADS 4
#define CHD   48
#define HH    128
#define WW    128
#define NPIX  16384
#define EPSV  1e-5f
#define NSPLIT 32

// ---------------- scratch (static device allocations) -----------------------
__device__ float g_bufA[BATCH * C3 * NPIX];
__device__ float g_bufB[BATCH * C3 * NPIX];
__device__ float g_bufC[BATCH * C1 * NPIX];
__device__ float g_bufD[BATCH * C1 * NPIX];
__device__ float g_sumsq[BATCH * 2 * C1];
__device__ float g_attn_part[32 * NSPLIT * CHD * CHD];
__device__ float g_attn[32 * CHD * CHD];
__device__ float g_M[BATCH * C1 * C1];      // fused proj_w @ blockdiag(attn)

// ---------------- LayerNorm over channel dim (per pixel) --------------------
__global__ void __launch_bounds__(256) ln_kernel(
    const float* __restrict__ x, float* __restrict__ out,
    const float* __restrict__ w, const float* __restrict__ b)
{
    int idx = blockIdx.x * 256 + threadIdx.x;
    int bb = idx >> 14;
    int p  = idx & (NPIX - 1);
    const float* xp = x + (size_t)bb * C1 * NPIX + p;
    float s = 0.f, s2 = 0.f;
    #pragma unroll 4
    for (int c = 0; c < C1; c++) {
        float v = xp[(size_t)c * NPIX];
        s += v; s2 = fmaf(v, v, s2);
    }
    float mu  = s * (1.f / C1);
    float var = fmaxf(s2 * (1.f / C1) - mu * mu, 0.f);
    float inv = rsqrtf(var + EPSV);
    float* op = out + (size_t)bb * C1 * NPIX + p;
    #pragma unroll 4
    for (int c = 0; c < C1; c++) {
        op[(size_t)c * NPIX] = (xp[(size_t)c * NPIX] - mu) * inv * w[c] + b[c];
    }
}

// ---------------- common PTX helpers ----------------------------------------
__device__ __forceinline__ void mma_tf32(float* c, const uint32_t* a, const uint32_t* b) {
    asm volatile(
        "mma.sync.aligned.m16n8k8.row.col.f32.tf32.tf32.f32 "
        "{%0,%1,%2,%3}, {%4,%5,%6,%7}, {%8,%9}, {%0,%1,%2,%3};\n"
        : "+f"(c[0]), "+f"(c[1]), "+f"(c[2]), "+f"(c[3])
        : "r"(a[0]), "r"(a[1]), "r"(a[2]), "r"(a[3]), "r"(b[0]), "r"(b[1]));
}
__device__ __forceinline__ void cp16(void* s, const void* g) {
    uint32_t sa = (uint32_t)__cvta_generic_to_shared(s);
    asm volatile("cp.async.cg.shared.global [%0], [%1], 16;\n" :: "r"(sa), "l"(g));
}
__device__ __forceinline__ uint32_t f2tf(float f) {
    uint32_t u; asm("cvt.rna.tf32.f32 %0, %1;" : "=r"(u) : "f"(f)); return u;
}

// ---------------- tf32 tensor-core GEMM, A in fragment-permuted smem --------
// FUSE: 0 = bias, 1 = bias+GELU, 2 = bias+residual
#define ASTAGE  2048                 // 64x32 floats, fragment-ordered
#define BSTRIDE 264
#define BSTAGE  (32 * BSTRIDE)
#define GEMM_SMEM ((2 * (ASTAGE + BSTAGE)) * 4)

template<int FUSE>
__global__ void __launch_bounds__(256) gemm_tf32_kernel(
    const float* __restrict__ in, float* __restrict__ out,
    const float* __restrict__ W, const float* __restrict__ bias,
    const float* __restrict__ resid, int M, int K,
    int in_bstride, int in_coff, int w_bstride)
{
    extern __shared__ float dsm[];
    float* As = dsm;                    // [2][ASTAGE]
    float* Bs = dsm + 2 * ASTAGE;       // [2][32][264]

    const int tid  = threadIdx.x;
    const int lane = tid & 31;
    const int wrp  = tid >> 5;
    const int n0   = blockIdx.x * 256;
    const int m0   = blockIdx.y * 64;
    const int bb   = blockIdx.z;
    const float* inb = in + ((size_t)bb * in_bstride + in_coff) * NPIX + n0;
    const float* Wb  = W + (size_t)bb * w_bstride;

    float acc[4][4][4];
    #pragma unroll
    for (int mt = 0; mt < 4; mt++)
        #pragma unroll
        for (int nt = 0; nt < 4; nt++)
            #pragma unroll
            for (int i = 0; i < 4; i++) acc[mt][nt][i] = 0.f;

    float aregs[8];
    // slot s = (g*4+mt)*32 + l  holds  W[r][c],W[r+8][c],W[r][c+4],W[r+8][c+4]
    //   r = m0 + mt*16 + (l>>2),  c = k0 + g*8 + (l&3)
    auto ldgA = [&](int k0) {
        #pragma unroll
        for (int i = 0; i < 2; i++) {
            int s = tid + i * 256;
            int l = s & 31, qq = s >> 5;
            int g = qq >> 2, mt = qq & 3;
            int r = m0 + mt * 16 + (l >> 2);
            int c = k0 + g * 8 + (l & 3);
            const float* wp = Wb + (size_t)r * K + c;
            aregs[i * 4 + 0] = __ldg(wp);
            aregs[i * 4 + 1] = __ldg(wp + (size_t)8 * K);
            aregs[i * 4 + 2] = __ldg(wp + 4);
            aregs[i * 4 + 3] = __ldg(wp + (size_t)8 * K + 4);
        }
    };
    auto stsA = [&](int st) {
        #pragma unroll
        for (int i = 0; i < 2; i++) {
            int s = tid + i * 256;
            *(float4*)(As + st * ASTAGE + s * 4) =
                make_float4(aregs[i*4], aregs[i*4+1], aregs[i*4+2], aregs[i*4+3]);
        }
    };
    auto cpB = [&](int k0, int st) {
        #pragma unroll
        for (int i = 0; i < 8; i++) {
            int l  = tid + i * 256;
            int r  = l >> 6;
            int c4 = (l & 63) * 4;
            cp16(Bs + st * BSTAGE + r * BSTRIDE + c4,
                 inb + (size_t)(k0 + r) * NPIX + c4);
        }
    };

    ldgA(0); stsA(0);
    cpB(0, 0);
    asm volatile("cp.async.commit_group;\n" ::);

    for (int k0 = 0; k0 < K; k0 += 32) {
        int st = (k0 >> 5) & 1;
        bool has_next = (k0 + 32 < K);
        if (has_next) {
            ldgA(k0 + 32);
            cpB(k0 + 32, st ^ 1);
            asm volatile("cp.async.commit_group;\n" ::);
            asm volatile("cp.async.wait_group 1;\n" ::);
        } else {
            asm volatile("cp.async.wait_all;\n" ::);
        }
        __syncthreads();

        const float*    Af = As + st * ASTAGE;
        const uint32_t* Bu = (const uint32_t*)(Bs + st * BSTAGE);
        #pragma unroll
        for (int g = 0; g < 4; g++) {
            const int kr = g * 8 + (lane & 3);
            uint32_t a[4][4], b[4][2];
            #pragma unroll
            for (int mt = 0; mt < 4; mt++) {
                float4 af = *(const float4*)(Af + ((g * 4 + mt) * 32 + lane) * 4);
                a[mt][0] = __float_as_uint(af.x);
                a[mt][1] = __float_as_uint(af.y);
                a[mt][2] = __float_as_uint(af.z);
                a[mt][3] = __float_as_uint(af.w);
            }
            #pragma unroll
            for (int nt = 0; nt < 4; nt++) {
                int nc = wrp * 32 + nt * 8 + (lane >> 2);
                b[nt][0] = Bu[kr * BSTRIDE + nc];
                b[nt][1] = Bu[(kr + 4) * BSTRIDE + nc];
            }
            #pragma unroll
            for (int mt = 0; mt < 4; mt++)
                #pragma unroll
                for (int nt = 0; nt < 4; nt++)
                    mma_tf32(acc[mt][nt], a[mt], b[nt]);
        }
        if (has_next) stsA(st ^ 1);
        __syncthreads();
    }

    #pragma unroll
    for (int mt = 0; mt < 4; mt++) {
        int r0 = m0 + mt * 16 + (lane >> 2);
        int r1 = r0 + 8;
        float bv0 = __ldg(&bias[r0]);
        float bv1 = __ldg(&bias[r1]);
        float* o0 = out + ((size_t)bb * M + r0) * NPIX + n0;
        float* o1 = out + ((size_t)bb * M + r1) * NPIX + n0;
        #pragma unroll
        for (int nt = 0; nt < 4; nt++) {
            int col = wrp * 32 + nt * 8 + (lane & 3) * 2;
            float v0 = acc[mt][nt][0] + bv0;
            float v1 = acc[mt][nt][1] + bv0;
            float v2 = acc[mt][nt][2] + bv1;
            float v3 = acc[mt][nt][3] + bv1;
            if (FUSE == 1) {
                v0 = 0.5f * v0 * (1.f + erff(v0 * 0.70710678118654752f));
                v1 = 0.5f * v1 * (1.f + erff(v1 * 0.70710678118654752f));
                v2 = 0.5f * v2 * (1.f + erff(v2 * 0.70710678118654752f));
                v3 = 0.5f * v3 * (1.f + erff(v3 * 0.70710678118654752f));
            }
            if (FUSE == 2) {
                const float* rr0 = resid + ((size_t)bb * M + r0) * NPIX + n0;
                const float* rr1 = resid + ((size_t)bb * M + r1) * NPIX + n0;
                float2 q0 = *(const float2*)(rr0 + col);
                float2 q1 = *(const float2*)(rr1 + col);
                v0 += q0.x; v1 += q0.y; v2 += q1.x; v3 += q1.y;
            }
            *(float2*)(o0 + col) = make_float2(v0, v1);
            *(float2*)(o1 + col) = make_float2(v2, v3);
        }
    }
}

// ---------------- depthwise 3x3 conv: warp-per-row + shuffle halo -----------
template<int RATIO, bool SUMSQ>
__global__ void __launch_bounds__(256) dwconv_kernel(
    const float* __restrict__ in, float* __restrict__ out,
    const float* __restrict__ wt, const float* __restrict__ bias,
    const float* __restrict__ prompt)
{
    const int warp = threadIdx.x >> 5;
    const int lane = threadIdx.x & 31;
    int rowIdx = blockIdx.x * 8 + warp;
    int y    = rowIdx & (HH - 1);
    int rest = rowIdx >> 7;
    int c    = rest % C3;
    int bb   = rest / C3;
    const int x0 = lane * 4;

    const float* ip = in + ((size_t)bb * (C3 / RATIO) + c / RATIO) * NPIX;
    const float* wp = wt + c * 9;
    float w[9];
    #pragma unroll
    for (int i = 0; i < 9; i++) w[i] = __ldg(&wp[i]);

    float bv = __ldg(&bias[c]);
    if (prompt != nullptr)
        bv += __ldg(&prompt[((c % C1) / CHD) * CHD + (c % CHD)]);
    float o0 = bv, o1 = bv, o2 = bv, o3 = bv;

    #pragma unroll
    for (int dy = -1; dy <= 1; dy++) {
        int yy = y + dy;
        if ((unsigned)yy < (unsigned)HH) {
            float4 m = *(const float4*)(ip + yy * WW + x0);
            float L = __shfl_up_sync(0xffffffffu, m.w, 1);
            float R = __shfl_down_sync(0xffffffffu, m.x, 1);
            if (lane == 0)  L = 0.f;
            if (lane == 31) R = 0.f;
            float w0 = w[(dy + 1) * 3 + 0];
            float w1 = w[(dy + 1) * 3 + 1];
            float w2 = w[(dy + 1) * 3 + 2];
            o0 = fmaf(w0, L,   fmaf(w1, m.x, fmaf(w2, m.y, o0)));
            o1 = fmaf(w0, m.x, fmaf(w1, m.y, fmaf(w2, m.z, o1)));
            o2 = fmaf(w0, m.y, fmaf(w1, m.z, fmaf(w2, m.w, o2)));
            o3 = fmaf(w0, m.z, fmaf(w1, m.w, fmaf(w2, R,   o3)));
        }
    }
    *(float4*)(out + ((size_t)bb * C3 + c) * NPIX + y * WW + x0) =
        make_float4(o0, o1, o2, o3);

    if (SUMSQ) {
        float ssq = o0 * o0 + o1 * o1 + o2 * o2 + o3 * o3;
        __shared__ float red[8];
        #pragma unroll
        for (int off = 16; off > 0; off >>= 1)
            ssq += __shfl_down_sync(0xffffffffu, ssq, off);
        if (lane == 0) red[warp] = ssq;
        __syncthreads();
        if (threadIdx.x == 0 && c < 2 * C1) {
            float t = 0.f;
            #pragma unroll
            for (int wv = 0; wv < 8; wv++) t += red[wv];
            atomicAdd(&g_sumsq[bb * 2 * C1 + c], t);
        }
    }
}

// ---------------- grouped 3x3 conv 192->576: 1 input read -> 3 outputs ------
__global__ void __launch_bounds__(256) dwconv3_kernel(
    const float* __restrict__ in, float* __restrict__ out,
    const float* __restrict__ wt, const float* __restrict__ bias)
{
    const int warp = threadIdx.x >> 5;
    const int lane = threadIdx.x & 31;
    int rowIdx = blockIdx.x * 8 + warp;        // over BATCH*C1*HH
    int y    = rowIdx & (HH - 1);
    int rest = rowIdx >> 7;
    int ci   = rest % C1;
    int bb   = rest / C1;
    const int x0 = lane * 4;

    const float* ip = in + ((size_t)bb * C1 + ci) * NPIX;
    float w[3][9];
    float o[3][4];
    #pragma unroll
    for (int r = 0; r < 3; r++) {
        const float* wp = wt + (ci * 3 + r) * 9;
        #pragma unroll
        for (int i = 0; i < 9; i++) w[r][i] = __ldg(&wp[i]);
        float bv = __ldg(&bias[ci * 3 + r]);
        o[r][0] = bv; o[r][1] = bv; o[r][2] = bv; o[r][3] = bv;
    }

    #pragma unroll
    for (int dy = -1; dy <= 1; dy++) {
        int yy = y + dy;
        if ((unsigned)yy < (unsigned)HH) {
            float4 m = *(const float4*)(ip + yy * WW + x0);
            float L = __shfl_up_sync(0xffffffffu, m.w, 1);
            float R = __shfl_down_sync(0xffffffffu, m.x, 1);
            if (lane == 0)  L = 0.f;
            if (lane == 31) R = 0.f;
            #pragma unroll
            for (int r = 0; r < 3; r++) {
                float w0 = w[r][(dy + 1) * 3 + 0];
                float w1 = w[r][(dy + 1) * 3 + 1];
                float w2 = w[r][(dy + 1) * 3 + 2];
                o[r][0] = fmaf(w0, L,   fmaf(w1, m.x, fmaf(w2, m.y, o[r][0])));
                o[r][1] = fmaf(w0, m.x, fmaf(w1, m.y, fmaf(w2, m.z, o[r][1])));
                o[r][2] = fmaf(w0, m.y, fmaf(w1, m.z, fmaf(w2, m.w, o[r][2])));
                o[r][3] = fmaf(w0, m.z, fmaf(w1, m.w, fmaf(w2, R,   o[r][3])));
            }
        }
    }
    #pragma unroll
    for (int r = 0; r < 3; r++)
        *(float4*)(out + ((size_t)bb * C3 + ci * 3 + r) * NPIX + y * WW + x0) =
            make_float4(o[r][0], o[r][1], o[r][2], o[r][3]);
}

// ---------------- QK^T via 3xtf32 tensor cores (fp32-accurate) --------------
// grid (32 bh, NSPLIT), 64 threads (2 warps; warp w owns n-tiles 3w..3w+2).
// K per CTA = NPIX/NSPLIT = 512, chunks of 32, double-buffered cp.async.
#define QKS 36   // row stride (floats): bank = 4*mrow + kc, conflict-free
__global__ void __launch_bounds__(64) qk_mma_kernel(const float* __restrict__ qkv)
{
    __shared__ float Qs[2][CHD][QKS];
    __shared__ float Ks[2][CHD][QKS];
    const int bh = blockIdx.x, split = blockIdx.y;
    const int bb = bh >> 2, h = bh & 3;
    const int CSPL = NPIX / NSPLIT;   // 512
    const float* qb = qkv + ((size_t)bb * C3 + h * CHD) * NPIX + split * CSPL;
    const float* kb = qb + (size_t)C1 * NPIX;
    const int tid  = threadIdx.x;
    const int lane = tid & 31;
    const int wrp  = tid >> 5;
    const int kc   = lane & 3;
    const int mrow = lane >> 2;

    float acc[3][3][4];
    #pragma unroll
    for (int mt = 0; mt < 3; mt++)
        #pragma unroll
        for (int j = 0; j < 3; j++)
            #pragma unroll
            for (int i = 0; i < 4; i++) acc[mt][j][i] = 0.f;

    auto loadc = [&](int ch, int st) {
        #pragma unroll
        for (int i = 0; i < 6; i++) {
            int s  = tid + i * 64;     // 0..383
            int r  = s >> 3;
            int c4 = (s & 7) * 4;
            cp16(&Qs[st][r][c4], qb + (size_t)r * NPIX + ch + c4);
            cp16(&Ks[st][r][c4], kb + (size_t)r * NPIX + ch + c4);
        }
    };

    loadc(0, 0);
    asm volatile("cp.async.commit_group;\n" ::);

    for (int c0 = 0; c0 < CSPL; c0 += 32) {
        int st = (c0 >> 5) & 1;
        if (c0 + 32 < CSPL) {
            loadc(c0 + 32, st ^ 1);
            asm volatile("cp.async.commit_group;\n" ::);
            asm volatile("cp.async.wait_group 1;\n" ::);
        } else {
            asm volatile("cp.async.wait_all;\n" ::);
        }
        __syncthreads();

        #pragma unroll
        for (int g = 0; g < 4; g++) {
            const int kr = g * 8 + kc;
            uint32_t ahi[3][4], alo[3][4];
            #pragma unroll
            for (int mt = 0; mt < 3; mt++) {
                float v0 = Qs[st][mt * 16 + mrow][kr];
                float v1 = Qs[st][mt * 16 + mrow + 8][kr];
                float v2 = Qs[st][mt * 16 + mrow][kr + 4];
                float v3 = Qs[st][mt * 16 + mrow + 8][kr + 4];
                ahi[mt][0] = f2tf(v0); alo[mt][0] = f2tf(v0 - __uint_as_float(ahi[mt][0]));
                ahi[mt][1] = f2tf(v1); alo[mt][1] = f2tf(v1 - __uint_as_float(ahi[mt][1]));
                ahi[mt][2] = f2tf(v2); alo[mt][2] = f2tf(v2 - __uint_as_float(ahi[mt][2]));
                ahi[mt][3] = f2tf(v3); alo[mt][3] = f2tf(v3 - __uint_as_float(ahi[mt][3]));
            }
            uint32_t bhi[3][2], blo[3][2];
            #pragma unroll
            for (int j = 0; j < 3; j++) {
                int nt = wrp * 3 + j;
                float u0 = Ks[st][nt * 8 + mrow][kr];
                float u1 = Ks[st][nt * 8 + mrow][kr + 4];
                bhi[j][0] = f2tf(u0); blo[j][0] = f2tf(u0 - __uint_as_float(bhi[j][0]));
                bhi[j][1] = f2tf(u1); blo[j][1] = f2tf(u1 - __uint_as_float(bhi[j][1]));
            }
            #pragma unroll
            for (int mt = 0; mt < 3; mt++)
                #pragma unroll
                for (int j = 0; j < 3; j++) {
                    mma_tf32(acc[mt][j], ahi[mt], bhi[j]);
                    mma_tf32(acc[mt][j], ahi[mt], blo[j]);
                    mma_tf32(acc[mt][j], alo[mt], bhi[j]);
                }
        }
        __syncthreads();
    }

    float* op = g_attn_part + ((size_t)bh * NSPLIT + split) * CHD * CHD;
    #pragma unroll
    for (int mt = 0; mt < 3; mt++)
        #pragma unroll
        for (int j = 0; j < 3; j++) {
            int nt = wrp * 3 + j;
            int m = mt * 16 + mrow;
            int n = nt * 8 + kc * 2;
            op[m * CHD + n]           = acc[mt][j][0];
            op[m * CHD + n + 1]       = acc[mt][j][1];
            op[(m + 8) * CHD + n]     = acc[mt][j][2];
            op[(m + 8) * CHD + n + 1] = acc[mt][j][3];
        }
}

// ---------------- reduce partials + normalize + temperature + softmax -------
__global__ void __launch_bounds__(256) attn_softmax_kernel(const float* __restrict__ temp)
{
    const int bh = blockIdx.x;
    const int bb = bh >> 2, h = bh & 3;
    __shared__ float sA[CHD * CHD];
    const int tid = threadIdx.x;
    const float tpr = temp[h];
    for (int i = tid; i < CHD * CHD; i += 256) {
        float s = 0.f;
        #pragma unroll
        for (int sp = 0; sp < NSPLIT; sp++)
            s += g_attn_part[((size_t)bh * NSPLIT + sp) * CHD * CHD + i];
        int c = i / CHD, d = i - c * CHD;
        float nq = fmaxf(sqrtf(g_sumsq[bb * 384 + h * CHD + c]), 1e-12f);
        float nk = fmaxf(sqrtf(g_sumsq[bb * 384 + C1 + h * CHD + d]), 1e-12f);
        sA[i] = s / (nq * nk) * tpr;
    }
    __syncthreads();
    if (tid < CHD) {
        float mx = -1e30f;
        #pragma unroll
        for (int d = 0; d < CHD; d++) mx = fmaxf(mx, sA[tid * CHD + d]);
        float e[CHD];
        float ssum = 0.f;
        #pragma unroll
        for (int d = 0; d < CHD; d++) {
            e[d] = expf(sA[tid * CHD + d] - mx);
            ssum += e[d];
        }
        float inv = 1.f / ssum;
        #pragma unroll
        for (int d = 0; d < CHD; d++)
            g_attn[(size_t)bh * CHD * CHD + tid * CHD + d] = e[d] * inv;
    }
}

// ---------------- M[b] = proj_w @ blockdiag(attn[b]) ------------------------
__global__ void __launch_bounds__(256) buildM_kernel(const float* __restrict__ pw)
{
    int idx = blockIdx.x * 256 + threadIdx.x;
    int ci = idx % C1;
    int rest = idx / C1;
    int oc = rest % C1;
    int bb = rest / C1;
    int h = ci / CHD, d = ci % CHD;
    const float* a = g_attn + ((size_t)(bb * 4 + h)) * CHD * CHD + d;
    const float* w = pw + (size_t)oc * C1 + h * CHD;
    float s = 0.f;
    #pragma unroll
    for (int cc = 0; cc < CHD; cc++)
        s = fmaf(w[cc], a[(size_t)cc * CHD], s);
    g_M[((size_t)bb * C1 + oc) * C1 + ci] = s;
}

// ---------------- launch ----------------------------------------------------
extern "C" void kernel_launch(void* const* d_in, const int* in_sizes, int n_in,
                              void* d_out, int out_size)
{
    const float* x       = (const float*)d_in[0];
    const float* ln1_w   = (const float*)d_in[1];
    const float* ln1_b   = (const float*)d_in[2];
    const float* qkv_w   = (const float*)d_in[3];
    const float* qkv_b   = (const float*)d_in[4];
    const float* qkv_dww = (const float*)d_in[5];
    const float* qkv_dwb = (const float*)d_in[6];
    const float* temp    = (const float*)d_in[7];
    const float* prompt  = (const float*)d_in[8];
    const float* proj_w  = (const float*)d_in[9];
    const float* proj_b  = (const float*)d_in[10];
    const float* ln2_w   = (const float*)d_in[11];
    const float* ln2_b   = (const float*)d_in[12];
    const float* dw1_w   = (const float*)d_in[13];
    const float* dw1_b   = (const float*)d_in[14];
    const float* pm_w    = (const float*)d_in[15];
    const float* pm_b    = (const float*)d_in[16];
    const float* dw2_w   = (const float*)d_in[17];
    const float* dw2_b   = (const float*)d_in[18];
    const float* po_w    = (const float*)d_in[19];
    const float* po_b    = (const float*)d_in[20];
    float* out = (float*)d_out;

    void *pA, *pB, *pC, *pD, *pS, *pM;
    cudaGetSymbolAddress(&pA, g_bufA);
    cudaGetSymbolAddress(&pB, g_bufB);
    cudaGetSymbolAddress(&pC, g_bufC);
    cudaGetSymbolAddress(&pD, g_bufD);
    cudaGetSymbolAddress(&pS, g_sumsq);
    cudaGetSymbolAddress(&pM, g_M);
    float* bufA = (float*)pA;
    float* bufB = (float*)pB;
    float* bufC = (float*)pC;
    float* bufD = (float*)pD;
    float* Mptr = (float*)pM;

    cudaFuncSetAttribute(gemm_tf32_kernel<0>, cudaFuncAttributeMaxDynamicSharedMemorySize, GEMM_SMEM);
    cudaFuncSetAttribute(gemm_tf32_kernel<1>, cudaFuncAttributeMaxDynamicSharedMemorySize, GEMM_SMEM);
    cudaFuncSetAttribute(gemm_tf32_kernel<2>, cudaFuncAttributeMaxDynamicSharedMemorySize, GEMM_SMEM);

    const int dwGrid  = BATCH * C3 * HH / 8;   // warp-per-row, 8 warps/block
    const int dw3Grid = BATCH * C1 * HH / 8;

    // ---- attention branch ----
    ln_kernel<<<BATCH * NPIX / 256, 256>>>(x, bufC, ln1_w, ln1_b);
    gemm_tf32_kernel<0><<<dim3(NPIX / 256, C3 / 64, BATCH), 256, GEMM_SMEM>>>(
        bufC, bufA, qkv_w, qkv_b, nullptr, C3, C1, C1, 0, 0);
    cudaMemsetAsync(pS, 0, BATCH * 2 * C1 * sizeof(float));
    dwconv_kernel<1, true><<<dwGrid, 256>>>(bufA, bufB, qkv_dww, qkv_dwb, prompt);
    qk_mma_kernel<<<dim3(32, NSPLIT), 64>>>(bufB);
    attn_softmax_kernel<<<32, 256>>>(temp);
    buildM_kernel<<<BATCH * C1 * C1 / 256, 256>>>(proj_w);
    // y1 = x + M @ v   (v = channels 384..575 of bufB)
    gemm_tf32_kernel<2><<<dim3(NPIX / 256, C1 / 64, BATCH), 256, GEMM_SMEM>>>(
        bufB, bufD, Mptr, proj_b, x, C1, C1, C3, 2 * C1, C1 * C1);

    // ---- FFN branch ----
    ln_kernel<<<BATCH * NPIX / 256, 256>>>(bufD, bufC, ln2_w, ln2_b);
    dwconv3_kernel<<<dw3Grid, 256>>>(bufC, bufA, dw1_w, dw1_b);
    gemm_tf32_kernel<1><<<dim3(NPIX / 256, C3 / 64, BATCH), 256, GEMM_SMEM>>>(
        bufA, bufB, pm_w, pm_b, nullptr, C3, C3, C3, 0, 0);
    dwconv_kernel<1, false><<<dwGrid, 256>>>(bufB, bufA, dw2_w, dw2_b, nullptr);
    gemm_tf32_kernel<2><<<dim3(NPIX / 256, C1 / 64, BATCH), 256, GEMM_SMEM>>>(
        bufA, out, po_w, po_b, bufD, C1, C3, C3, 0, 0);
}

// round 13
// speedup vs baseline: 1.1149x; 1.1149x over previous
#include <cuda_runtime.h>
#include <math.h>
#include <stdint.h>

#define BATCH 8
#define C1    192
#define C3    576
#define HEADS 4
#define CHD   48
#define HH    128
#define WW    128
#define NPIX  16384
#define EPSV  1e-5f
#define NSPLIT 32

// ---------------- scratch (static device allocations) -----------------------
__device__ float g_bufA[BATCH * C3 * NPIX];
__device__ float g_bufB[BATCH * C3 * NPIX];
__device__ float g_bufC[BATCH * C1 * NPIX];
__device__ float g_bufD[BATCH * C1 * NPIX];
__device__ float g_sumsq[BATCH * 2 * C1];
__device__ float g_attn_part[32 * NSPLIT * CHD * CHD];
__device__ float g_attn[32 * CHD * CHD];
__device__ float g_M[BATCH * C1 * C1];      // fused proj_w @ blockdiag(attn)

// ---------------- LayerNorm over channel dim (per pixel) --------------------
__global__ void __launch_bounds__(256) ln_kernel(
    const float* __restrict__ x, float* __restrict__ out,
    const float* __restrict__ w, const float* __restrict__ b)
{
    int idx = blockIdx.x * 256 + threadIdx.x;
    int bb = idx >> 14;
    int p  = idx & (NPIX - 1);
    const float* xp = x + (size_t)bb * C1 * NPIX + p;
    float s = 0.f, s2 = 0.f;
    #pragma unroll 4
    for (int c = 0; c < C1; c++) {
        float v = xp[(size_t)c * NPIX];
        s += v; s2 = fmaf(v, v, s2);
    }
    float mu  = s * (1.f / C1);
    float var = fmaxf(s2 * (1.f / C1) - mu * mu, 0.f);
    float inv = rsqrtf(var + EPSV);
    float* op = out + (size_t)bb * C1 * NPIX + p;
    #pragma unroll 4
    for (int c = 0; c < C1; c++) {
        op[(size_t)c * NPIX] = (xp[(size_t)c * NPIX] - mu) * inv * w[c] + b[c];
    }
}

// ---------------- common PTX helpers ----------------------------------------
__device__ __forceinline__ void mma_tf32(float* c, const uint32_t* a, const uint32_t* b) {
    asm volatile(
        "mma.sync.aligned.m16n8k8.row.col.f32.tf32.tf32.f32 "
        "{%0,%1,%2,%3}, {%4,%5,%6,%7}, {%8,%9}, {%0,%1,%2,%3};\n"
        : "+f"(c[0]), "+f"(c[1]), "+f"(c[2]), "+f"(c[3])
        : "r"(a[0]), "r"(a[1]), "r"(a[2]), "r"(a[3]), "r"(b[0]), "r"(b[1]));
}
__device__ __forceinline__ void cp16(void* s, const void* g) {
    uint32_t sa = (uint32_t)__cvta_generic_to_shared(s);
    asm volatile("cp.async.cg.shared.global [%0], [%1], 16;\n" :: "r"(sa), "l"(g));
}
__device__ __forceinline__ uint32_t f2tf(float f) {
    uint32_t u; asm("cvt.rna.tf32.f32 %0, %1;" : "=r"(u) : "f"(f)); return u;
}

// ---------------- tf32 tensor-core GEMM with cp.async double buffering ------
// FUSE: 0 = bias, 1 = bias+GELU, 2 = bias+residual   (R9 proven structure)
#define ASTRIDE 36
#define BSTRIDE 264
#define ASTAGE  (64 * ASTRIDE)
#define BSTAGE  (32 * BSTRIDE)
#define GEMM_SMEM ((2 * (ASTAGE + BSTAGE)) * 4)

template<int FUSE>
__global__ void __launch_bounds__(256) gemm_tf32_kernel(
    const float* __restrict__ in, float* __restrict__ out,
    const float* __restrict__ W, const float* __restrict__ bias,
    const float* __restrict__ resid, int M, int K,
    int in_bstride, int in_coff, int w_bstride)
{
    extern __shared__ float dsm[];
    float* As = dsm;
    float* Bs = dsm + 2 * ASTAGE;

    const int tid  = threadIdx.x;
    const int lane = tid & 31;
    const int wrp  = tid >> 5;
    const int n0   = blockIdx.x * 256;
    const int m0   = blockIdx.y * 64;
    const int bb   = blockIdx.z;
    const float* inb = in + ((size_t)bb * in_bstride + in_coff) * NPIX + n0;
    const float* Wb  = W + (size_t)bb * w_bstride;

    const int am = tid >> 2;
    const int ak = (tid & 3) * 8;

    float acc[4][4][4];
    #pragma unroll
    for (int mt = 0; mt < 4; mt++)
        #pragma unroll
        for (int nt = 0; nt < 4; nt++)
            #pragma unroll
            for (int i = 0; i < 4; i++) acc[mt][nt][i] = 0.f;

    auto load_stage = [&](int k0, int st) {
        const float* wr = Wb + (size_t)(m0 + am) * K + k0 + ak;
        float* ad = As + st * ASTAGE + am * ASTRIDE + ak;
        cp16(ad, wr);
        cp16(ad + 4, wr + 4);
        #pragma unroll
        for (int i = 0; i < 8; i++) {
            int l  = tid + i * 256;
            int r  = l >> 6;
            int c4 = (l & 63) * 4;
            cp16(Bs + st * BSTAGE + r * BSTRIDE + c4,
                 inb + (size_t)(k0 + r) * NPIX + c4);
        }
    };

    load_stage(0, 0);
    asm volatile("cp.async.commit_group;\n" ::);

    for (int k0 = 0; k0 < K; k0 += 32) {
        int st = (k0 >> 5) & 1;
        if (k0 + 32 < K) {
            load_stage(k0 + 32, st ^ 1);
            asm volatile("cp.async.commit_group;\n" ::);
            asm volatile("cp.async.wait_group 1;\n" ::);
        } else {
            asm volatile("cp.async.wait_all;\n" ::);
        }
        __syncthreads();

        const uint32_t* Au = (const uint32_t*)(As + st * ASTAGE);
        const uint32_t* Bu = (const uint32_t*)(Bs + st * BSTAGE);
        #pragma unroll
        for (int kk = 0; kk < 32; kk += 8) {
            const int kr   = kk + (lane & 3);
            const int mrow = lane >> 2;
            uint32_t a[4][4], b[4][2];
            #pragma unroll
            for (int mt = 0; mt < 4; mt++) {
                int mb = mt * 16 + mrow;
                a[mt][0] = Au[mb * ASTRIDE + kr];
                a[mt][1] = Au[(mb + 8) * ASTRIDE + kr];
                a[mt][2] = Au[mb * ASTRIDE + kr + 4];
                a[mt][3] = Au[(mb + 8) * ASTRIDE + kr + 4];
            }
            #pragma unroll
            for (int nt = 0; nt < 4; nt++) {
                int nc = wrp * 32 + nt * 8 + (lane >> 2);
                b[nt][0] = Bu[kr * BSTRIDE + nc];
                b[nt][1] = Bu[(kr + 4) * BSTRIDE + nc];
            }
            #pragma unroll
            for (int mt = 0; mt < 4; mt++)
                #pragma unroll
                for (int nt = 0; nt < 4; nt++)
                    mma_tf32(acc[mt][nt], a[mt], b[nt]);
        }
        __syncthreads();
    }

    #pragma unroll
    for (int mt = 0; mt < 4; mt++) {
        int r0 = m0 + mt * 16 + (lane >> 2);
        int r1 = r0 + 8;
        float bv0 = __ldg(&bias[r0]);
        float bv1 = __ldg(&bias[r1]);
        float* o0 = out + ((size_t)bb * M + r0) * NPIX + n0;
        float* o1 = out + ((size_t)bb * M + r1) * NPIX + n0;
        #pragma unroll
        for (int nt = 0; nt < 4; nt++) {
            int col = wrp * 32 + nt * 8 + (lane & 3) * 2;
            float v0 = acc[mt][nt][0] + bv0;
            float v1 = acc[mt][nt][1] + bv0;
            float v2 = acc[mt][nt][2] + bv1;
            float v3 = acc[mt][nt][3] + bv1;
            if (FUSE == 1) {
                v0 = 0.5f * v0 * (1.f + erff(v0 * 0.70710678118654752f));
                v1 = 0.5f * v1 * (1.f + erff(v1 * 0.70710678118654752f));
                v2 = 0.5f * v2 * (1.f + erff(v2 * 0.70710678118654752f));
                v3 = 0.5f * v3 * (1.f + erff(v3 * 0.70710678118654752f));
            }
            if (FUSE == 2) {
                const float* rr0 = resid + ((size_t)bb * M + r0) * NPIX + n0;
                const float* rr1 = resid + ((size_t)bb * M + r1) * NPIX + n0;
                float2 q0 = *(const float2*)(rr0 + col);
                float2 q1 = *(const float2*)(rr1 + col);
                v0 += q0.x; v1 += q0.y; v2 += q1.x; v3 += q1.y;
            }
            *(float2*)(o0 + col) = make_float2(v0, v1);
            *(float2*)(o1 + col) = make_float2(v2, v3);
        }
    }
}

// ---------------- depthwise / grouped 3x3 conv: warp-per-row + shuffle halo -
template<int RATIO, bool SUMSQ>
__global__ void __launch_bounds__(256) dwconv_kernel(
    const float* __restrict__ in, float* __restrict__ out,
    const float* __restrict__ wt, const float* __restrict__ bias,
    const float* __restrict__ prompt)
{
    const int warp = threadIdx.x >> 5;
    const int lane = threadIdx.x & 31;
    int rowIdx = blockIdx.x * 8 + warp;
    int y    = rowIdx & (HH - 1);
    int rest = rowIdx >> 7;
    int c    = rest % C3;
    int bb   = rest / C3;
    const int x0 = lane * 4;

    const float* ip = in + ((size_t)bb * (C3 / RATIO) + c / RATIO) * NPIX;
    const float* wp = wt + c * 9;
    float w[9];
    #pragma unroll
    for (int i = 0; i < 9; i++) w[i] = __ldg(&wp[i]);

    float bv = __ldg(&bias[c]);
    if (prompt != nullptr)
        bv += __ldg(&prompt[((c % C1) / CHD) * CHD + (c % CHD)]);
    float o0 = bv, o1 = bv, o2 = bv, o3 = bv;

    #pragma unroll
    for (int dy = -1; dy <= 1; dy++) {
        int yy = y + dy;
        if ((unsigned)yy < (unsigned)HH) {
            float4 m = *(const float4*)(ip + yy * WW + x0);
            float L = __shfl_up_sync(0xffffffffu, m.w, 1);
            float R = __shfl_down_sync(0xffffffffu, m.x, 1);
            if (lane == 0)  L = 0.f;
            if (lane == 31) R = 0.f;
            float w0 = w[(dy + 1) * 3 + 0];
            float w1 = w[(dy + 1) * 3 + 1];
            float w2 = w[(dy + 1) * 3 + 2];
            o0 = fmaf(w0, L,   fmaf(w1, m.x, fmaf(w2, m.y, o0)));
            o1 = fmaf(w0, m.x, fmaf(w1, m.y, fmaf(w2, m.z, o1)));
            o2 = fmaf(w0, m.y, fmaf(w1, m.z, fmaf(w2, m.w, o2)));
            o3 = fmaf(w0, m.z, fmaf(w1, m.w, fmaf(w2, R,   o3)));
        }
    }
    *(float4*)(out + ((size_t)bb * C3 + c) * NPIX + y * WW + x0) =
        make_float4(o0, o1, o2, o3);

    if (SUMSQ) {
        float ssq = o0 * o0 + o1 * o1 + o2 * o2 + o3 * o3;
        __shared__ float red[8];
        #pragma unroll
        for (int off = 16; off > 0; off >>= 1)
            ssq += __shfl_down_sync(0xffffffffu, ssq, off);
        if (lane == 0) red[warp] = ssq;
        __syncthreads();
        if (threadIdx.x == 0 && c < 2 * C1) {
            float t = 0.f;
            #pragma unroll
            for (int wv = 0; wv < 8; wv++) t += red[wv];
            atomicAdd(&g_sumsq[bb * 2 * C1 + c], t);
        }
    }
}

// ---------------- QK^T via 3xtf32 tensor cores (fp32-accurate) --------------
#define QKS 36
__global__ void __launch_bounds__(64) qk_mma_kernel(const float* __restrict__ qkv)
{
    __shared__ float Qs[2][CHD][QKS];
    __shared__ float Ks[2][CHD][QKS];
    const int bh = blockIdx.x, split = blockIdx.y;
    const int bb = bh >> 2, h = bh & 3;
    const int CSPL = NPIX / NSPLIT;   // 512
    const float* qb = qkv + ((size_t)bb * C3 + h * CHD) * NPIX + split * CSPL;
    const float* kb = qb + (size_t)C1 * NPIX;
    const int tid  = threadIdx.x;
    const int lane = tid & 31;
    const int wrp  = tid >> 5;
    const int kc   = lane & 3;
    const int mrow = lane >> 2;

    float acc[3][3][4];
    #pragma unroll
    for (int mt = 0; mt < 3; mt++)
        #pragma unroll
        for (int j = 0; j < 3; j++)
            #pragma unroll
            for (int i = 0; i < 4; i++) acc[mt][j][i] = 0.f;

    auto loadc = [&](int ch, int st) {
        #pragma unroll
        for (int i = 0; i < 6; i++) {
            int s  = tid + i * 64;
            int r  = s >> 3;
            int c4 = (s & 7) * 4;
            cp16(&Qs[st][r][c4], qb + (size_t)r * NPIX + ch + c4);
            cp16(&Ks[st][r][c4], kb + (size_t)r * NPIX + ch + c4);
        }
    };

    loadc(0, 0);
    asm volatile("cp.async.commit_group;\n" ::);

    for (int c0 = 0; c0 < CSPL; c0 += 32) {
        int st = (c0 >> 5) & 1;
        if (c0 + 32 < CSPL) {
            loadc(c0 + 32, st ^ 1);
            asm volatile("cp.async.commit_group;\n" ::);
            asm volatile("cp.async.wait_group 1;\n" ::);
        } else {
            asm volatile("cp.async.wait_all;\n" ::);
        }
        __syncthreads();

        #pragma unroll
        for (int g = 0; g < 4; g++) {
            const int kr = g * 8 + kc;
            uint32_t ahi[3][4], alo[3][4];
            #pragma unroll
            for (int mt = 0; mt < 3; mt++) {
                float v0 = Qs[st][mt * 16 + mrow][kr];
                float v1 = Qs[st][mt * 16 + mrow + 8][kr];
                float v2 = Qs[st][mt * 16 + mrow][kr + 4];
                float v3 = Qs[st][mt * 16 + mrow + 8][kr + 4];
                ahi[mt][0] = f2tf(v0); alo[mt][0] = f2tf(v0 - __uint_as_float(ahi[mt][0]));
                ahi[mt][1] = f2tf(v1); alo[mt][1] = f2tf(v1 - __uint_as_float(ahi[mt][1]));
                ahi[mt][2] = f2tf(v2); alo[mt][2] = f2tf(v2 - __uint_as_float(ahi[mt][2]));
                ahi[mt][3] = f2tf(v3); alo[mt][3] = f2tf(v3 - __uint_as_float(ahi[mt][3]));
            }
            uint32_t bhi[3][2], blo[3][2];
            #pragma unroll
            for (int j = 0; j < 3; j++) {
                int nt = wrp * 3 + j;
                float u0 = Ks[st][nt * 8 + mrow][kr];
                float u1 = Ks[st][nt * 8 + mrow][kr + 4];
                bhi[j][0] = f2tf(u0); blo[j][0] = f2tf(u0 - __uint_as_float(bhi[j][0]));
                bhi[j][1] = f2tf(u1); blo[j][1] = f2tf(u1 - __uint_as_float(bhi[j][1]));
            }
            #pragma unroll
            for (int mt = 0; mt < 3; mt++)
                #pragma unroll
                for (int j = 0; j < 3; j++) {
                    mma_tf32(acc[mt][j], ahi[mt], bhi[j]);
                    mma_tf32(acc[mt][j], ahi[mt], blo[j]);
                    mma_tf32(acc[mt][j], alo[mt], bhi[j]);
                }
        }
        __syncthreads();
    }

    float* op = g_attn_part + ((size_t)bh * NSPLIT + split) * CHD * CHD;
    #pragma unroll
    for (int mt = 0; mt < 3; mt++)
        #pragma unroll
        for (int j = 0; j < 3; j++) {
            int nt = wrp * 3 + j;
            int m = mt * 16 + mrow;
            int n = nt * 8 + kc * 2;
            op[m * CHD + n]           = acc[mt][j][0];
            op[m * CHD + n + 1]       = acc[mt][j][1];
            op[(m + 8) * CHD + n]     = acc[mt][j][2];
            op[(m + 8) * CHD + n + 1] = acc[mt][j][3];
        }
}

// ---------------- reduce partials + normalize + temperature + softmax -------
__global__ void __launch_bounds__(256) attn_softmax_kernel(const float* __restrict__ temp)
{
    const int bh = blockIdx.x;
    const int bb = bh >> 2, h = bh & 3;
    __shared__ float sA[CHD * CHD];
    const int tid = threadIdx.x;
    const float tpr = temp[h];
    for (int i = tid; i < CHD * CHD; i += 256) {
        float s = 0.f;
        #pragma unroll
        for (int sp = 0; sp < NSPLIT; sp++)
            s += g_attn_part[((size_t)bh * NSPLIT + sp) * CHD * CHD + i];
        int c = i / CHD, d = i - c * CHD;
        float nq = fmaxf(sqrtf(g_sumsq[bb * 384 + h * CHD + c]), 1e-12f);
        float nk = fmaxf(sqrtf(g_sumsq[bb * 384 + C1 + h * CHD + d]), 1e-12f);
        sA[i] = s / (nq * nk) * tpr;
    }
    __syncthreads();
    if (tid < CHD) {
        float mx = -1e30f;
        #pragma unroll
        for (int d = 0; d < CHD; d++) mx = fmaxf(mx, sA[tid * CHD + d]);
        float e[CHD];
        float ssum = 0.f;
        #pragma unroll
        for (int d = 0; d < CHD; d++) {
            e[d] = expf(sA[tid * CHD + d] - mx);
            ssum += e[d];
        }
        float inv = 1.f / ssum;
        #pragma unroll
        for (int d = 0; d < CHD; d++)
            g_attn[(size_t)bh * CHD * CHD + tid * CHD + d] = e[d] * inv;
    }
}

// ---------------- M[b] = proj_w @ blockdiag(attn[b]) ------------------------
__global__ void __launch_bounds__(256) buildM_kernel(const float* __restrict__ pw)
{
    int idx = blockIdx.x * 256 + threadIdx.x;
    int ci = idx % C1;
    int rest = idx / C1;
    int oc = rest % C1;
    int bb = rest / C1;
    int h = ci / CHD, d = ci % CHD;
    const float* a = g_attn + ((size_t)(bb * 4 + h)) * CHD * CHD + d;
    const float* w = pw + (size_t)oc * C1 + h * CHD;
    float s = 0.f;
    #pragma unroll
    for (int cc = 0; cc < CHD; cc++)
        s = fmaf(w[cc], a[(size_t)cc * CHD], s);
    g_M[((size_t)bb * C1 + oc) * C1 + ci] = s;
}

// ---------------- launch ----------------------------------------------------
extern "C" void kernel_launch(void* const* d_in, const int* in_sizes, int n_in,
                              void* d_out, int out_size)
{
    const float* x       = (const float*)d_in[0];
    const float* ln1_w   = (const float*)d_in[1];
    const float* ln1_b   = (const float*)d_in[2];
    const float* qkv_w   = (const float*)d_in[3];
    const float* qkv_b   = (const float*)d_in[4];
    const float* qkv_dww = (const float*)d_in[5];
    const float* qkv_dwb = (const float*)d_in[6];
    const float* temp    = (const float*)d_in[7];
    const float* prompt  = (const float*)d_in[8];
    const float* proj_w  = (const float*)d_in[9];
    const float* proj_b  = (const float*)d_in[10];
    const float* ln2_w   = (const float*)d_in[11];
    const float* ln2_b   = (const float*)d_in[12];
    const float* dw1_w   = (const float*)d_in[13];
    const float* dw1_b   = (const float*)d_in[14];
    const float* pm_w    = (const float*)d_in[15];
    const float* pm_b    = (const float*)d_in[16];
    const float* dw2_w   = (const float*)d_in[17];
    const float* dw2_b   = (const float*)d_in[18];
    const float* po_w    = (const float*)d_in[19];
    const float* po_b    = (const float*)d_in[20];
    float* out = (float*)d_out;

    void *pA, *pB, *pC, *pD, *pS, *pM;
    cudaGetSymbolAddress(&pA, g_bufA);
    cudaGetSymbolAddress(&pB, g_bufB);
    cudaGetSymbolAddress(&pC, g_bufC);
    cudaGetSymbolAddress(&pD, g_bufD);
    cudaGetSymbolAddress(&pS, g_sumsq);
    cudaGetSymbolAddress(&pM, g_M);
    float* bufA = (float*)pA;
    float* bufB = (float*)pB;
    float* bufC = (float*)pC;
    float* bufD = (float*)pD;
    float* Mptr = (float*)pM;

    cudaFuncSetAttribute(gemm_tf32_kernel<0>, cudaFuncAttributeMaxDynamicSharedMemorySize, GEMM_SMEM);
    cudaFuncSetAttribute(gemm_tf32_kernel<1>, cudaFuncAttributeMaxDynamicSharedMemorySize, GEMM_SMEM);
    cudaFuncSetAttribute(gemm_tf32_kernel<2>, cudaFuncAttributeMaxDynamicSharedMemorySize, GEMM_SMEM);

    const int dwGrid = BATCH * C3 * HH / 8;   // warp-per-row, 8 warps/block

    // ---- attention branch ----
    ln_kernel<<<BATCH * NPIX / 256, 256>>>(x, bufC, ln1_w, ln1_b);
    gemm_tf32_kernel<0><<<dim3(NPIX / 256, C3 / 64, BATCH), 256, GEMM_SMEM>>>(
        bufC, bufA, qkv_w, qkv_b, nullptr, C3, C1, C1, 0, 0);
    cudaMemsetAsync(pS, 0, BATCH * 2 * C1 * sizeof(float));
    dwconv_kernel<1, true><<<dwGrid, 256>>>(bufA, bufB, qkv_dww, qkv_dwb, prompt);
    qk_mma_kernel<<<dim3(32, NSPLIT), 64>>>(bufB);
    attn_softmax_kernel<<<32, 256>>>(temp);
    buildM_kernel<<<BATCH * C1 * C1 / 256, 256>>>(proj_w);
    // y1 = x + M @ v   (v = channels 384..575 of bufB)
    gemm_tf32_kernel<2><<<dim3(NPIX / 256, C1 / 64, BATCH), 256, GEMM_SMEM>>>(
        bufB, bufD, Mptr, proj_b, x, C1, C1, C3, 2 * C1, C1 * C1);

    // ---- FFN branch ----
    ln_kernel<<<BATCH * NPIX / 256, 256>>>(bufD, bufC, ln2_w, ln2_b);
    dwconv_kernel<3, false><<<dwGrid, 256>>>(bufC, bufA, dw1_w, dw1_b, nullptr);
    gemm_tf32_kernel<1><<<dim3(NPIX / 256, C3 / 64, BATCH), 256, GEMM_SMEM>>>(
        bufA, bufB, pm_w, pm_b, nullptr, C3, C3, C3, 0, 0);
    dwconv_kernel<1, false><<<dwGrid, 256>>>(bufB, bufA, dw2_w, dw2_b, nullptr);
    gemm_tf32_kernel<2><<<dim3(NPIX / 256, C1 / 64, BATCH), 256, GEMM_SMEM>>>(
        bufA, out, po_w, po_b, bufD, C1, C3, C3, 0, 0);
}